// round 4
// baseline (speedup 1.0000x reference)
#include <cuda_runtime.h>
#include <cuda_fp16.h>
#include <cstdint>
#include <cstddef>

#define B_   512
#define IN_  4096
#define OUT_ 11008

// scratch (static device globals — no runtime allocation)
__device__ __align__(1024) __half g_W[(size_t)OUT_ * IN_];
__device__ __align__(1024) __half g_x[(size_t)B_ * IN_];

// ---------------- PTX helpers (sm_80-level only; no tcgen05) -----------------
__device__ __forceinline__ uint32_t smem_u32(const void* p) {
    uint32_t a;
    asm("{ .reg .u64 t; cvta.to.shared.u64 t, %1; cvt.u32.u64 %0, t; }"
        : "=r"(a) : "l"(p));
    return a;
}

#define CP16(dst, src) \
    asm volatile("cp.async.cg.shared.global [%0], [%1], 16;" :: "r"(dst), "l"(src))
#define CP_COMMIT() asm volatile("cp.async.commit_group;" ::: "memory")

__device__ __forceinline__ void ldsm_x4(uint32_t* r, uint32_t addr) {
    asm volatile("ldmatrix.sync.aligned.m8n8.x4.shared.b16 {%0,%1,%2,%3}, [%4];"
                 : "=r"(r[0]), "=r"(r[1]), "=r"(r[2]), "=r"(r[3]) : "r"(addr));
}

__device__ __forceinline__ void mma16816(float* c, const uint32_t* a, const uint32_t* b) {
    asm volatile(
        "mma.sync.aligned.m16n8k16.row.col.f32.f16.f16.f32 "
        "{%0,%1,%2,%3}, {%4,%5,%6,%7}, {%8,%9}, {%0,%1,%2,%3};\n"
        : "+f"(c[0]), "+f"(c[1]), "+f"(c[2]), "+f"(c[3])
        : "r"(a[0]), "r"(a[1]), "r"(a[2]), "r"(a[3]), "r"(b[0]), "r"(b[1]));
}

// ---------------- kernel 1: x fp32 -> fp16 -----------------------------------
__global__ void xconv_kernel(const float* __restrict__ x) {
    const int n4 = (B_ * IN_) / 4;
    int stride = gridDim.x * blockDim.x;
    for (int i = blockIdx.x * blockDim.x + threadIdx.x; i < n4; i += stride) {
        float4 v = reinterpret_cast<const float4*>(x)[i];
        __half2 lo = __floats2half2_rn(v.x, v.y);
        __half2 hi = __floats2half2_rn(v.z, v.w);
        uint2 o;
        o.x = *reinterpret_cast<uint32_t*>(&lo);
        o.y = *reinterpret_cast<uint32_t*>(&hi);
        reinterpret_cast<uint2*>(g_x)[i] = o;
    }
}

// ---------------- kernel 2: QINS dequant via 511-entry LUT -------------------
__global__ void dequant_kernel(const int* __restrict__ stored,
                               const int* __restrict__ sign,
                               const float* __restrict__ lmin_p,
                               const float* __restrict__ lmax_p) {
    __shared__ unsigned lut[512];
    float lmin = __ldg(lmin_p);
    float lmax = __ldg(lmax_p);
    for (int i = threadIdx.x; i < 511; i += blockDim.x) {
        int s = i - 255;
        int mag = s < 0 ? -s : s;
        float w = 0.0f;
        if (s != 0) {
            float nrm = (255.0f - (float)mag) * (1.0f / 254.0f);
            w = expf(lmin + nrm * (lmax - lmin));
            if (s < 0) w = -w;
        }
        unsigned hb = (unsigned)__half_as_ushort(__float2half_rn(w));
        lut[i] = hb | (hb << 16);   // dup both halves -> 1 PRMT packs a pair
    }
    __syncthreads();

    const int4* st4 = reinterpret_cast<const int4*>(stored);
    const int4* sg4 = reinterpret_cast<const int4*>(sign);
    uint4* w4 = reinterpret_cast<uint4*>(g_W);
    const size_t n8 = (size_t)OUT_ * IN_ / 8;
    size_t stride = (size_t)gridDim.x * blockDim.x;
    for (size_t i = (size_t)blockIdx.x * blockDim.x + threadIdx.x; i < n8; i += stride) {
        int4 a0 = st4[2 * i];
        int4 a1 = st4[2 * i + 1];
        int4 s0 = sg4[2 * i];
        int4 s1 = sg4[2 * i + 1];
        unsigned l0 = lut[s0.x * a0.x + 255];
        unsigned l1 = lut[s0.y * a0.y + 255];
        unsigned l2 = lut[s0.z * a0.z + 255];
        unsigned l3 = lut[s0.w * a0.w + 255];
        unsigned l4 = lut[s1.x * a1.x + 255];
        unsigned l5 = lut[s1.y * a1.y + 255];
        unsigned l6 = lut[s1.z * a1.z + 255];
        unsigned l7 = lut[s1.w * a1.w + 255];
        uint4 o;
        o.x = __byte_perm(l0, l1, 0x5410);
        o.y = __byte_perm(l2, l3, 0x5410);
        o.z = __byte_perm(l4, l5, 0x5410);
        o.w = __byte_perm(l6, l7, 0x5410);
        w4[i] = o;
    }
}

// ---------------- kernel 3: HMMA fp16 GEMM + fused epilogue ------------------
// C[512,11008] = x[512,4096] @ W[11008,4096]^T ; per-CTA tile 128x128, BK=32.
#define MT 128
#define NT 128
#define BK 32
#define NCHUNK (IN_ / BK)        // 128
#define AS_STRIDE 40             // halves per smem row (32 data + 8 pad)

__global__ void __launch_bounds__(256, 2)
gemm_kernel(const float* __restrict__ bias, const float* __restrict__ scale,
            float* __restrict__ out) {
    __shared__ __half sA[2][MT * AS_STRIDE];
    __shared__ __half sB[2][NT * AS_STRIDE];
    __shared__ float bias_s[NT], scale_s[NT];

    const int tid   = threadIdx.x;
    const int wid   = tid >> 5;
    const int lane  = tid & 31;
    const int ntile = blockIdx.x;   // 0..85
    const int mtile = blockIdx.y;   // 0..3
    const int wm = wid >> 2;        // 0..1 -> m offset wm*64
    const int wn = wid & 3;         // 0..3 -> n offset wn*32

    for (int i = tid; i < NT; i += 256) {
        bias_s[i]  = bias[ntile * NT + i];
        scale_s[i] = scale[ntile * NT + i];
    }

    // ---- cp.async geometry: 2 x 16B per thread per tile per chunk ----
    const __half* srcA[2];
    const __half* srcB[2];
    uint32_t dstA[2][2], dstB[2][2];
#pragma unroll
    for (int t = 0; t < 2; t++) {
        int idx = tid + t * 256;
        int row = idx >> 2;
        int c   = idx & 3;              // 16B chunk within 64B row
        srcA[t] = g_x + (size_t)(mtile * MT + row) * IN_ + c * 8;
        srcB[t] = g_W + (size_t)(ntile * NT + row) * IN_ + c * 8;
#pragma unroll
        for (int s = 0; s < 2; s++) {
            dstA[s][t] = smem_u32(&sA[s][row * AS_STRIDE + c * 8]);
            dstB[s][t] = smem_u32(&sB[s][row * AS_STRIDE + c * 8]);
        }
    }

    auto fill = [&](int chunk, int s) {
        int k0 = chunk * BK;
#pragma unroll
        for (int t = 0; t < 2; t++) {
            CP16(dstA[s][t], srcA[t] + k0);
            CP16(dstB[s][t], srcB[t] + k0);
        }
        CP_COMMIT();
    };

    // ---- ldmatrix address offsets (bytes, within a stage) ----
    const int lr = lane & 7;
    const int lj = lane >> 3;           // matrix group 0..3
    uint32_t aBase[2], bBase[2];
#pragma unroll
    for (int s = 0; s < 2; s++) {
        aBase[s] = smem_u32(sA[s]);
        bBase[s] = smem_u32(sB[s]);
    }
    // A x4: mats {(+0,k),( +8,k),(+0,k+8),(+8,k+8)}
    uint32_t aOff[2][4], bOff[2][2];
#pragma unroll
    for (int ks = 0; ks < 2; ks++) {
        int kk = ks * 16;
#pragma unroll
        for (int mf = 0; mf < 4; mf++) {
            int row = wm * 64 + mf * 16 + lr + (lj & 1) * 8;
            int col = kk + (lj >> 1) * 8;
            aOff[ks][mf] = (uint32_t)(row * AS_STRIDE + col) * 2;
        }
        // B x4: mats {(n+0,k),(n+0,k+8),(n+8,k),(n+8,k+8)}
#pragma unroll
        for (int nh = 0; nh < 2; nh++) {
            int nrow = wn * 32 + nh * 16 + lr + (lj >> 1) * 8;
            int col  = kk + (lj & 1) * 8;
            bOff[ks][nh] = (uint32_t)(nrow * AS_STRIDE + col) * 2;
        }
    }

    float acc[4][4][4];
#pragma unroll
    for (int a = 0; a < 4; a++)
#pragma unroll
        for (int b = 0; b < 4; b++)
#pragma unroll
            for (int q = 0; q < 4; q++) acc[a][b][q] = 0.0f;

    fill(0, 0);
    fill(1, 1);

    for (int i = 0; i < NCHUNK; i++) {
        const int s = i & 1;
        if (i < NCHUNK - 1) asm volatile("cp.async.wait_group 1;" ::: "memory");
        else                asm volatile("cp.async.wait_group 0;" ::: "memory");
        __syncthreads();

#pragma unroll
        for (int ks = 0; ks < 2; ks++) {
            uint32_t a_frag[4][4];
            uint32_t b_frag[4][2];
#pragma unroll
            for (int mf = 0; mf < 4; mf++)
                ldsm_x4(a_frag[mf], aBase[s] + aOff[ks][mf]);
#pragma unroll
            for (int nh = 0; nh < 2; nh++) {
                uint32_t r[4];
                ldsm_x4(r, bBase[s] + bOff[ks][nh]);
                b_frag[2 * nh][0]     = r[0];
                b_frag[2 * nh][1]     = r[1];
                b_frag[2 * nh + 1][0] = r[2];
                b_frag[2 * nh + 1][1] = r[3];
            }
#pragma unroll
            for (int mf = 0; mf < 4; mf++)
#pragma unroll
                for (int nf = 0; nf < 4; nf++)
                    mma16816(acc[mf][nf], a_frag[mf], b_frag[nf]);
        }

        __syncthreads();
        if (i + 2 < NCHUNK) fill(i + 2, s);
    }

    // ---- epilogue: (acc + bias) * scale, float2 stores ----
    const int lq = lane >> 2;        // row within frag
    const int lp = lane & 3;         // col pair
#pragma unroll
    for (int mf = 0; mf < 4; mf++) {
#pragma unroll
        for (int nf = 0; nf < 4; nf++) {
            int lcol = wn * 32 + nf * 8 + 2 * lp;
            int grow = mtile * MT + wm * 64 + mf * 16 + lq;
            size_t base = (size_t)grow * OUT_ + ntile * NT + lcol;
            float2 v0, v1;
            v0.x = (acc[mf][nf][0] + bias_s[lcol])     * scale_s[lcol];
            v0.y = (acc[mf][nf][1] + bias_s[lcol + 1]) * scale_s[lcol + 1];
            v1.x = (acc[mf][nf][2] + bias_s[lcol])     * scale_s[lcol];
            v1.y = (acc[mf][nf][3] + bias_s[lcol + 1]) * scale_s[lcol + 1];
            *reinterpret_cast<float2*>(out + base)             = v0;
            *reinterpret_cast<float2*>(out + base + 8 * OUT_)  = v1;
        }
    }
}

// ---------------- launch -----------------------------------------------------
extern "C" void kernel_launch(void* const* d_in, const int* in_sizes, int n_in,
                              void* d_out, int out_size) {
    const float* x      = (const float*)d_in[0];
    const int*   stored = (const int*)d_in[1];
    const int*   sign   = (const int*)d_in[2];
    const float* lmin   = (const float*)d_in[3];
    const float* lmax   = (const float*)d_in[4];
    const float* scale  = (const float*)d_in[5];
    const float* bias   = (const float*)d_in[6];
    float* out = (float*)d_out;

    xconv_kernel<<<512, 256>>>(x);
    dequant_kernel<<<2368, 256>>>(stored, sign, lmin, lmax);
    gemm_kernel<<<dim3(OUT_ / NT, B_ / MT), 256>>>(bias, scale, out);
}